// round 1
// baseline (speedup 1.0000x reference)
#include <cuda_runtime.h>
#include <cuda_bf16.h>
#include <math.h>

// ---------------- problem constants ----------------
#define H      3584
#define NH     28
#define NKV    4
#define D      128
#define GROUP  7           // NH / NKV
#define B      4
#define S      1024
#define T      (B*S)       // 4096
#define NB     512
#define BS     16
#define QKVD   ((NH + 2*NKV) * D)   // 4608
#define SCALE_ATT 0.08838834764831845f  // 1/sqrt(128)

#define CACHE_HALF ((size_t)NB * BS * NKV * D)   // 4,194,304 floats per (k|v)

// ---------------- scratch (device globals; no allocation allowed) ----------------
__device__ float g_qkv[(size_t)T * QKVD];       // 4096 x 4608
__device__ float g_ctx[(size_t)T * NH * D];     // 4096 x 3584

// ---------------------------------------------------------------------------
// Tiled fp32 GEMM:  C[M,N] = A[M,K] @ W[N,K]^T (+ bias[n])
// BM=128, BN=64, BK=16, 256 threads, 8x4 micro-tile per thread.
// Requires: M % 128 == 0, N % 64 == 0, K % 16 == 0 (true for all uses here).
// ---------------------------------------------------------------------------
__global__ __launch_bounds__(256)
void gemm_bias_kernel(const float* __restrict__ A,
                      const float* __restrict__ W,
                      const float* __restrict__ bias,
                      float* __restrict__ C,
                      int M, int N, int K)
{
    const int BM = 128, BN = 64, BK = 16;
    __shared__ float As[BK][BM];
    __shared__ float Ws[BK][BN];

    const int tid = threadIdx.x;
    const int m0 = blockIdx.y * BM;
    const int n0 = blockIdx.x * BN;

    const int tm = tid >> 4;   // 0..15 -> rows tm*8 .. tm*8+7
    const int tn = tid & 15;   // 0..15 -> cols tn*4 .. tn*4+3

    const int lrow = tid >> 2;        // 0..63
    const int lk4  = (tid & 3) * 4;   // 0,4,8,12

    float acc[8][4];
    #pragma unroll
    for (int i = 0; i < 8; i++)
        #pragma unroll
        for (int j = 0; j < 4; j++) acc[i][j] = 0.f;

    for (int k0 = 0; k0 < K; k0 += BK) {
        // load A tile (128 x 16), two passes of 64 rows, float4 along K
        #pragma unroll
        for (int p = 0; p < 2; p++) {
            int r = lrow + p * 64;
            float4 v = *(const float4*)&A[(size_t)(m0 + r) * K + k0 + lk4];
            As[lk4 + 0][r] = v.x;
            As[lk4 + 1][r] = v.y;
            As[lk4 + 2][r] = v.z;
            As[lk4 + 3][r] = v.w;
        }
        // load W tile (64 x 16)
        {
            float4 v = *(const float4*)&W[(size_t)(n0 + lrow) * K + k0 + lk4];
            Ws[lk4 + 0][lrow] = v.x;
            Ws[lk4 + 1][lrow] = v.y;
            Ws[lk4 + 2][lrow] = v.z;
            Ws[lk4 + 3][lrow] = v.w;
        }
        __syncthreads();

        #pragma unroll
        for (int k = 0; k < BK; k++) {
            float a[8], w[4];
            *(float4*)&a[0] = *(const float4*)&As[k][tm * 8];
            *(float4*)&a[4] = *(const float4*)&As[k][tm * 8 + 4];
            *(float4*)&w[0] = *(const float4*)&Ws[k][tn * 4];
            #pragma unroll
            for (int i = 0; i < 8; i++)
                #pragma unroll
                for (int j = 0; j < 4; j++)
                    acc[i][j] += a[i] * w[j];
        }
        __syncthreads();
    }

    const int n = n0 + tn * 4;
    float b0 = 0.f, b1 = 0.f, b2 = 0.f, b3 = 0.f;
    if (bias) { b0 = bias[n]; b1 = bias[n+1]; b2 = bias[n+2]; b3 = bias[n+3]; }

    #pragma unroll
    for (int i = 0; i < 8; i++) {
        int m = m0 + tm * 8 + i;
        float4 o;
        o.x = acc[i][0] + b0;
        o.y = acc[i][1] + b1;
        o.z = acc[i][2] + b2;
        o.w = acc[i][3] + b3;
        *(float4*)&C[(size_t)m * N + n] = o;
    }
}

// ---------------------------------------------------------------------------
// RoPE applied in-place to Q (NH heads) and K (NKV heads) sections of g_qkv.
// One thread per (t, head, d<64).
// ---------------------------------------------------------------------------
__global__ void rope_kernel(const int* __restrict__ positions,
                            float* __restrict__ qkv)
{
    int idx = blockIdx.x * blockDim.x + threadIdx.x;
    const int total = T * (NH + NKV) * 64;
    if (idx >= total) return;
    int d    = idx & 63;
    int rest = idx >> 6;
    int head = rest % (NH + NKV);
    int t    = rest / (NH + NKV);

    float inv_freq = powf(10000.f, -(float)(2 * d) / 128.f);
    float ang = (float)positions[t] * inv_freq;
    float s, c;
    sincosf(ang, &s, &c);

    float* base = qkv + (size_t)t * QKVD + (size_t)head * D;
    float x1 = base[d];
    float x2 = base[d + 64];
    base[d]      = x1 * c - x2 * s;
    base[d + 64] = x2 * c + x1 * s;
}

// ---------------------------------------------------------------------------
// Copy the input kv_cache into the output cache region (float4 copy).
// ---------------------------------------------------------------------------
__global__ void cache_copy_kernel(const float4* __restrict__ src,
                                  float4* __restrict__ dst, int n4)
{
    int i = blockIdx.x * blockDim.x + threadIdx.x;
    if (i < n4) dst[i] = src[i];
}

// ---------------------------------------------------------------------------
// Scatter post-RoPE K and raw V into the output cache by slot_mapping.
// One thread per (t, kv, d).
// ---------------------------------------------------------------------------
__global__ void cache_scatter_kernel(const float* __restrict__ qkv,
                                     const int* __restrict__ slot_mapping,
                                     float* __restrict__ cache_out)
{
    int idx = blockIdx.x * blockDim.x + threadIdx.x;
    const int total = T * NKV * D;
    if (idx >= total) return;
    int d    = idx & (D - 1);
    int rest = idx >> 7;
    int kv   = rest & (NKV - 1);
    int t    = rest >> 2;

    int slot = slot_mapping[t];
    size_t src = (size_t)t * QKVD + (size_t)NH * D + (size_t)kv * D + d;
    size_t dst = ((size_t)slot * NKV + kv) * D + d;
    cache_out[dst]              = qkv[src];                     // K
    cache_out[CACHE_HALF + dst] = qkv[src + (size_t)NKV * D];   // V
}

// ---------------------------------------------------------------------------
// GQA causal attention, prefill. One warp per (token, head), streaming
// online-softmax over keys 0..qi. K/V read from post-RoPE g_qkv (L2-resident).
// ---------------------------------------------------------------------------
__global__ __launch_bounds__(256)
void attn_kernel(const float* __restrict__ qkv, float* __restrict__ ctx)
{
    int gw   = (blockIdx.x * blockDim.x + threadIdx.x) >> 5;
    int lane = threadIdx.x & 31;
    if (gw >= T * NH) return;
    int t = gw / NH;
    int h = gw - t * NH;
    int b  = t >> 10;          // t / S
    int qi = t & (S - 1);      // t % S
    int kv = h / GROUP;

    const float* qp = qkv + (size_t)t * QKVD + (size_t)h * D;
    float q0 = qp[lane], q1 = qp[lane + 32], q2 = qp[lane + 64], q3 = qp[lane + 96];

    const float* kbase = qkv + (size_t)(b << 10) * QKVD + (size_t)NH * D + (size_t)kv * D;
    const float* vbase = kbase + (size_t)NKV * D;

    float m = -1e30f, l = 0.f;
    float a0 = 0.f, a1 = 0.f, a2 = 0.f, a3 = 0.f;

    for (int s = 0; s <= qi; s++) {
        const float* kp = kbase + (size_t)s * QKVD;
        float dot = q0 * kp[lane] + q1 * kp[lane + 32]
                  + q2 * kp[lane + 64] + q3 * kp[lane + 96];
        #pragma unroll
        for (int o = 16; o > 0; o >>= 1)
            dot += __shfl_xor_sync(0xffffffffu, dot, o);
        float sc = dot * SCALE_ATT;

        float mn   = fmaxf(m, sc);
        float corr = __expf(m - mn);
        float p    = __expf(sc - mn);
        l = l * corr + p;

        const float* vp = vbase + (size_t)s * QKVD;
        a0 = a0 * corr + p * vp[lane];
        a1 = a1 * corr + p * vp[lane + 32];
        a2 = a2 * corr + p * vp[lane + 64];
        a3 = a3 * corr + p * vp[lane + 96];
        m = mn;
    }

    float inv = 1.f / l;
    float* op = ctx + (size_t)t * (NH * D) + (size_t)h * D;
    op[lane]      = a0 * inv;
    op[lane + 32] = a1 * inv;
    op[lane + 64] = a2 * inv;
    op[lane + 96] = a3 * inv;
}

// ---------------------------------------------------------------------------
// launch
// ---------------------------------------------------------------------------
extern "C" void kernel_launch(void* const* d_in, const int* in_sizes, int n_in,
                              void* d_out, int out_size)
{
    const int*   positions    = (const int*)  d_in[0];
    const float* hidden       = (const float*)d_in[1];
    const float* kv_cache     = (const float*)d_in[2];
    const int*   slot_mapping = (const int*)  d_in[4];
    // weights are the last three inputs regardless of whether is_prefill
    // materializes as a buffer
    const int wb = n_in - 3;
    const float* w_qkv = (const float*)d_in[wb];
    const float* b_qkv = (const float*)d_in[wb + 1];
    const float* w_o   = (const float*)d_in[wb + 2];

    float* out       = (float*)d_out;
    float* cache_out = out + (size_t)T * H;

    float* qkv_buf = nullptr;
    float* ctx_buf = nullptr;
    cudaGetSymbolAddress((void**)&qkv_buf, g_qkv);
    cudaGetSymbolAddress((void**)&ctx_buf, g_ctx);

    // 1. QKV projection: [T, QKVD] = hidden [T,H] @ w_qkv[QKVD,H]^T + b
    {
        dim3 grid(QKVD / 64, T / 128);
        gemm_bias_kernel<<<grid, 256>>>(hidden, w_qkv, b_qkv, qkv_buf, T, QKVD, H);
    }

    // 2. RoPE on Q and K sections, in place
    {
        int total = T * (NH + NKV) * 64;
        rope_kernel<<<(total + 255) / 256, 256>>>(positions, qkv_buf);
    }

    // 3. Cache: copy original, then scatter new K/V
    {
        int n4 = (int)(2 * CACHE_HALF / 4);
        cache_copy_kernel<<<(n4 + 255) / 256, 256>>>((const float4*)kv_cache,
                                                     (float4*)cache_out, n4);
        int total = T * NKV * D;
        cache_scatter_kernel<<<(total + 255) / 256, 256>>>(qkv_buf, slot_mapping,
                                                           cache_out);
    }

    // 4. Attention -> ctx
    {
        int warps = T * NH;
        int threads = warps * 32;
        attn_kernel<<<(threads + 255) / 256, 256>>>(qkv_buf, ctx_buf);
    }

    // 5. Output projection: out [T,H] = ctx [T, NH*D] @ w_o[H, NH*D]^T
    {
        dim3 grid(H / 64, T / 128);
        gemm_bias_kernel<<<grid, 256>>>(ctx_buf, w_o, nullptr, out, T, H, NH * D);
    }
}